// round 12
// baseline (speedup 1.0000x reference)
#include <cuda_runtime.h>
#include <math.h>
#include <cstdint>

#define GATES 256
#define OBS_  20
#define MB    64
#define NT    256
#define NW    8      // warps
#define CC    8      // batch cols per warp

typedef unsigned long long ULL;

// ---- SMEM layout (floats) ----
#define OFF_W    0                     // [128][256] swizzled (see stageW)
#define OFF_BIAS (OFF_W + 128*256)     // [256] permuted
#define OFF_WE   (OFF_BIAS + 256)      // [2][64]
#define OFF_BE   (OFF_WE + 128)        // [64]
#define OFF_WFC  (OFF_BE + 64)         // [2][64]
#define OFF_BFC  (OFF_WFC + 128)       // [2]+pad
#define OFF_X    (OFF_BFC + 4)         // NW * [64][8]
#define OFF_H    (OFF_X + NW*64*CC)    // NW * [64][8]
#define OFF_OBS  (OFF_H + NW*64*CC)    // NW * [40][8]
#define SMEM_FLOATS (OFF_OBS + NW*40*CC)
#define SMEM_BYTES  (SMEM_FLOATS * 4)

#define FMA_F32X2(d, a, b, c_) \
    asm("fma.rn.f32x2 %0, %1, %2, %3;" : "=l"(d) : "l"(a), "l"(b), "l"(c_))
#define PACK_DUP(out, v) \
    asm("mov.b64 %0, {%1, %1};" : "=l"(out) : "r"(v))
#define UNPACK2(lo, hi, in) \
    asm("mov.b64 {%0, %1}, %2;" : "=r"(lo), "=r"(hi) : "l"(in))

__device__ __forceinline__ float sigf(float x) {
    return __fdividef(1.0f, 1.0f + __expf(-x));
}
__device__ __forceinline__ float tanh_(float x) {
    float a = fabsf(x);
    float e = __expf(2.0f * a);
    float t = 1.0f - __fdividef(2.0f, e + 1.0f);
    return copysignf(t, x);
}

__global__ void __launch_bounds__(NT, 1)
vanilla_lstm_kernel(const float* __restrict__ obs,
                    const float* __restrict__ W_emb,  const float* __restrict__ b_emb,
                    const float* __restrict__ Wih_e,  const float* __restrict__ Whh_e,
                    const float* __restrict__ bih_e,  const float* __restrict__ bhh_e,
                    const float* __restrict__ Wih_d,  const float* __restrict__ Whh_d,
                    const float* __restrict__ bih_d,  const float* __restrict__ bhh_d,
                    const float* __restrict__ W_fc,   const float* __restrict__ b_fc,
                    float* __restrict__ out, int pred_len)
{
    extern __shared__ float sm[];
    float* sW    = sm + OFF_W;
    float* sBias = sm + OFF_BIAS;
    float* sWe   = sm + OFF_WE;
    float* sBe   = sm + OFF_BE;
    float* sWfc  = sm + OFF_WFC;
    float* sBfc  = sm + OFF_BFC;

    const int tid  = threadIdx.x;
    const int lane = tid & 31;
    const int w    = tid >> 5;
    const int b0   = blockIdx.x * MB;

    // per-warp strips: [64 k rows][8 cols]
    float4* xW4 = (float4*)(sm + OFF_X) + w * 128;   // 2 float4 per k row
    float4* hW4 = (float4*)(sm + OFF_H) + w * 128;
    float*  oW  = sm + OFF_OBS + w * 40 * CC;

    // ---- stage small params ----
    if (tid < 128) sWe[tid] = W_emb[(tid & 63) * 2 + (tid >> 6)];
    if (tid < 64)  sBe[tid] = b_emb[tid];
    if (tid < 128) sWfc[tid] = W_fc[tid];
    if (tid < 2)   sBfc[tid] = b_fc[tid];

    // obs: strip[w][r][c] with c = b & 7, w = b >> 3
    for (int i = tid; i < MB * 40; i += NT) {
        int b = i / 40, r = i % 40;
        sm[OFF_OBS + (b >> 3) * 40 * CC + r * CC + (b & 7)] =
            obs[(size_t)(b0 + b) * 40 + r];
    }

    // ---- weight staging, lane-swizzled (identical to prior passing round) ----
    auto stageW = [&](const float* Wih, const float* Whh,
                      const float* bih, const float* bhh) {
        for (int i = tid; i < GATES * 64; i += NT) {
            int row = i >> 6, k = i & 63;
            int g = row >> 6, rem = row & 63;
            int l = rem >> 1, d = rem & 1;
            int sz = (l >> 2) & 1;
            int phys = (2 * l + ((g >> 1) ^ sz)) * 4 + (g & 1) * 2 + d;
            sW[k * GATES + phys]        = Wih[i];
            sW[(64 + k) * GATES + phys] = Whh[i];
        }
        for (int row = tid; row < GATES; row += NT) {
            int g = row >> 6, rem = row & 63;
            sBias[(rem >> 1) * 8 + g * 2 + (rem & 1)] = bih[row] + bhh[row];
        }
    };
    stageW(Wih_e, Whh_e, bih_e, bhh_e);
    __syncthreads();

    // ---- per-lane hoisted constants ----
    const int swz = (lane >> 2) & 1;
    const char* wAx = (const char*)sW + (2 * lane + swz) * 16;       // g0,g1
    const char* wBx = (const char*)sW + (2 * lane + 1 - swz) * 16;   // g2,g3
    const char* wAh = wAx + 64 * 1024;
    const char* wBh = wBx + 64 * 1024;

    const int e0 = 2 * lane, e1 = 2 * lane + 1;
    float we00 = sWe[e0], we01 = sWe[64 + e0], be0 = sBe[e0];
    float we10 = sWe[e1], we11 = sWe[64 + e1], be1 = sBe[e1];
    float wfc00 = sWfc[e0], wfc01 = sWfc[e1];
    float wfc10 = sWfc[64 + e0], wfc11 = sWfc[64 + e1];
    float bfc0 = sBfc[0], bfc1 = sBfc[1];

    ULL biasv[4];
    #pragma unroll
    for (int g = 0; g < 4; g++)
        biasv[g] = *(const ULL*)(sBias + lane * 8 + g * 2);

    // zero h strip (lane owns k rows e0, e1)
    hW4[2 * e0] = make_float4(0.f,0.f,0.f,0.f);
    hW4[2 * e0 + 1] = make_float4(0.f,0.f,0.f,0.f);
    hW4[2 * e1] = make_float4(0.f,0.f,0.f,0.f);
    hW4[2 * e1 + 1] = make_float4(0.f,0.f,0.f,0.f);

    // embedded x for lane's 2 e-rows x 8 cols
    float4 xa0, xa1, xb0, xb1;
    auto embed_regs = [&](const float* p0, const float* p1) {
        float va[8], vb[8];
        #pragma unroll
        for (int j = 0; j < 8; j++) {
            va[j] = fmaxf(fmaf(p0[j], we00, fmaf(p1[j], we01, be0)), 0.f);
            vb[j] = fmaxf(fmaf(p0[j], we10, fmaf(p1[j], we11, be1)), 0.f);
        }
        xa0 = make_float4(va[0], va[1], va[2], va[3]);
        xa1 = make_float4(va[4], va[5], va[6], va[7]);
        xb0 = make_float4(vb[0], vb[1], vb[2], vb[3]);
        xb1 = make_float4(vb[4], vb[5], vb[6], vb[7]);
    };
    auto embed_obs = [&](int tt) {
        float p0[8], p1[8];
        *(float4*)(p0)     = *(const float4*)(oW + (2 * tt) * CC);
        *(float4*)(p0 + 4) = *(const float4*)(oW + (2 * tt) * CC + 4);
        *(float4*)(p1)     = *(const float4*)(oW + (2 * tt + 1) * CC);
        *(float4*)(p1 + 4) = *(const float4*)(oW + (2 * tt + 1) * CC + 4);
        embed_regs(p0, p1);
    };

    // 64-k GEMM half over 8 cols
    auto gemm64 = [&](const float4* src, const char* wA, const char* wB,
                      ULL a[4][8]) {
        #pragma unroll 4
        for (int k = 0; k < 64; k++) {
            float4 xlo = src[2 * k];
            float4 xhi = src[2 * k + 1];
            ULL xq[8];
            PACK_DUP(xq[0], __float_as_uint(xlo.x));
            PACK_DUP(xq[1], __float_as_uint(xlo.y));
            PACK_DUP(xq[2], __float_as_uint(xlo.z));
            PACK_DUP(xq[3], __float_as_uint(xlo.w));
            PACK_DUP(xq[4], __float_as_uint(xhi.x));
            PACK_DUP(xq[5], __float_as_uint(xhi.y));
            PACK_DUP(xq[6], __float_as_uint(xhi.z));
            PACK_DUP(xq[7], __float_as_uint(xhi.w));
            float4 w01 = *(const float4*)(wA + k * 1024);
            float4 w23 = *(const float4*)(wB + k * 1024);
            ULL wq0 = *(ULL*)&w01.x, wq1 = *(ULL*)&w01.z;
            ULL wq2 = *(ULL*)&w23.x, wq3 = *(ULL*)&w23.z;
            #pragma unroll
            for (int b = 0; b < 8; b++) {
                FMA_F32X2(a[0][b], wq0, xq[b], a[0][b]);
                FMA_F32X2(a[1][b], wq1, xq[b], a[1][b]);
                FMA_F32X2(a[2][b], wq2, xq[b], a[2][b]);
                FMA_F32X2(a[3][b], wq3, xq[b], a[3][b]);
            }
        }
    };

    float c[2][8], hv[2][8];
    #pragma unroll
    for (int d = 0; d < 2; d++)
        #pragma unroll
        for (int b = 0; b < 8; b++) c[d][b] = 0.0f;

    auto epi_col = [&](ULL a[4][8], int b) {
        unsigned i0, i1, f0, f1, g0, g1, o0, o1;
        UNPACK2(i0, i1, a[0][b]);
        UNPACK2(f0, f1, a[1][b]);
        UNPACK2(g0, g1, a[2][b]);
        UNPACK2(o0, o1, a[3][b]);
        {
            float ig = sigf(__uint_as_float(i0));
            float fg = sigf(__uint_as_float(f0));
            float gg = tanh_(__uint_as_float(g0));
            float og = sigf(__uint_as_float(o0));
            float cn = fmaf(fg, c[0][b], ig * gg);
            c[0][b] = cn;
            hv[0][b] = og * tanh_(cn);
        }
        {
            float ig = sigf(__uint_as_float(i1));
            float fg = sigf(__uint_as_float(f1));
            float gg = tanh_(__uint_as_float(g1));
            float og = sigf(__uint_as_float(o1));
            float cn = fmaf(fg, c[1][b], ig * gg);
            c[1][b] = cn;
            hv[1][b] = og * tanh_(cn);
        }
    };

    // ---- prologue ----
    embed_obs(0);
    xW4[2 * e0] = xa0; xW4[2 * e0 + 1] = xa1;
    xW4[2 * e1] = xb0; xW4[2 * e1 + 1] = xb1;
    __syncwarp();

    const int TOT = OBS_ + pred_len;
    for (int t = 0; t < TOT; t++) {
        if (t == OBS_) {                 // enc -> dec swap (only global syncs)
            __syncthreads();
            stageW(Wih_d, Whh_d, bih_d, bhh_d);
            __syncthreads();
            #pragma unroll
            for (int g = 0; g < 4; g++)
                biasv[g] = *(const ULL*)(sBias + lane * 8 + g * 2);
        }

        ULL acc[4][8];
        #pragma unroll
        for (int g = 0; g < 4; g++)
            #pragma unroll
            for (int b = 0; b < 8; b++) acc[g][b] = biasv[g];

        gemm64(xW4, wAx, wBx, acc);
        gemm64(hW4, wAh, wBh, acc);

        bool do_embed = false;
        if (t < OBS_ - 1) { embed_obs(t + 1); do_embed = true; }

        #pragma unroll
        for (int b = 0; b < 8; b++) epi_col(acc, b);

        if (t >= OBS_) {
            // FC: 16-value butterfly over 64 hidden (2 per lane)
            float r[16];
            #pragma unroll
            for (int b = 0; b < 8; b++) {
                r[b]     = fmaf(hv[0][b], wfc00, hv[1][b] * wfc01);
                r[8 + b] = fmaf(hv[0][b], wfc10, hv[1][b] * wfc11);
            }
            #pragma unroll
            for (int off = 16; off >= 1; off >>= 1)
                #pragma unroll
                for (int j = 0; j < 16; j++)
                    r[j] += __shfl_xor_sync(0xffffffffu, r[j], off);
            float p0[8], p1[8];
            #pragma unroll
            for (int b = 0; b < 8; b++) { p0[b] = r[b] + bfc0; p1[b] = r[8 + b] + bfc1; }

            if (lane < 8) {
                float o0v = 0.f, o1v = 0.f;
                #pragma unroll
                for (int b = 0; b < 8; b++)
                    if (lane == b) { o0v = p0[b]; o1v = p1[b]; }
                size_t o = ((size_t)(b0 + w * 8 + lane) * pred_len + (t - OBS_)) * 2;
                *(float2*)(out + o) = make_float2(o0v, o1v);
            }
            if (t < TOT - 1) { embed_regs(p0, p1); do_embed = true; }
        }

        __syncwarp();                    // all lanes done reading strips
        if (t < TOT - 1) {
            hW4[2 * e0]     = make_float4(hv[0][0], hv[0][1], hv[0][2], hv[0][3]);
            hW4[2 * e0 + 1] = make_float4(hv[0][4], hv[0][5], hv[0][6], hv[0][7]);
            hW4[2 * e1]     = make_float4(hv[1][0], hv[1][1], hv[1][2], hv[1][3]);
            hW4[2 * e1 + 1] = make_float4(hv[1][4], hv[1][5], hv[1][6], hv[1][7]);
        }
        if (do_embed) {                  // t==OBS_-1 keeps x = emb(obs[19])
            xW4[2 * e0] = xa0; xW4[2 * e0 + 1] = xa1;
            xW4[2 * e1] = xb0; xW4[2 * e1 + 1] = xb1;
        }
        __syncwarp();
    }
}

extern "C" void kernel_launch(void* const* d_in, const int* in_sizes, int n_in,
                              void* d_out, int out_size)
{
    const float* obs   = (const float*)d_in[0];
    const float* W_emb = (const float*)d_in[1];
    const float* b_emb = (const float*)d_in[2];
    const float* Wih_e = (const float*)d_in[3];
    const float* Whh_e = (const float*)d_in[4];
    const float* bih_e = (const float*)d_in[5];
    const float* bhh_e = (const float*)d_in[6];
    const float* Wih_d = (const float*)d_in[7];
    const float* Whh_d = (const float*)d_in[8];
    const float* bih_d = (const float*)d_in[9];
    const float* bhh_d = (const float*)d_in[10];
    const float* W_fc  = (const float*)d_in[11];
    const float* b_fc  = (const float*)d_in[12];
    float* out = (float*)d_out;

    int B = in_sizes[0] / (OBS_ * 2);
    int pred_len = out_size / (B * 2);

    cudaFuncSetAttribute(vanilla_lstm_kernel,
                         cudaFuncAttributeMaxDynamicSharedMemorySize, SMEM_BYTES);

    int grid = B / MB;
    vanilla_lstm_kernel<<<grid, NT, SMEM_BYTES>>>(
        obs, W_emb, b_emb, Wih_e, Whh_e, bih_e, bhh_e,
        Wih_d, Whh_d, bih_d, bhh_d, W_fc, b_fc, out, pred_len);
}

// round 14
// speedup vs baseline: 1.0052x; 1.0052x over previous
#include <cuda_runtime.h>
#include <math.h>
#include <cstdint>

#define GATES 256
#define OBS_  20
#define MB    64
#define NT    256
#define NW    8      // warps
#define CC    8      // batch cols per warp

typedef unsigned long long ULL;

// ---- SMEM layout (floats) ----
#define OFF_W    0                     // [128][256] swizzled (see stageW)
#define OFF_BIAS (OFF_W + 128*256)     // [256] permuted
#define OFF_WE   (OFF_BIAS + 256)      // [2][64]
#define OFF_BE   (OFF_WE + 128)        // [64]
#define OFF_WFC  (OFF_BE + 64)         // [2][64]
#define OFF_BFC  (OFF_WFC + 128)       // [2]+pad
#define OFF_X    (OFF_BFC + 4)         // NW * [64][8]
#define OFF_H    (OFF_X + NW*64*CC)    // NW * [64][8]
#define OFF_OBS  (OFF_H + NW*64*CC)    // NW * [40][8]
#define SMEM_FLOATS (OFF_OBS + NW*40*CC)
#define SMEM_BYTES  (SMEM_FLOATS * 4)

#define FMA_F32X2(d, a, b, c_) \
    asm("fma.rn.f32x2 %0, %1, %2, %3;" : "=l"(d) : "l"(a), "l"(b), "l"(c_))
#define PACK_DUP(out, v) \
    asm("mov.b64 %0, {%1, %1};" : "=l"(out) : "r"(v))
#define UNPACK2(lo, hi, in) \
    asm("mov.b64 {%0, %1}, %2;" : "=r"(lo), "=r"(hi) : "l"(in))

__device__ __forceinline__ float sigf(float x) {
    return __fdividef(1.0f, 1.0f + __expf(-x));
}
__device__ __forceinline__ float tanh_(float x) {
    float a = fabsf(x);
    float e = __expf(2.0f * a);
    float t = 1.0f - __fdividef(2.0f, e + 1.0f);
    return copysignf(t, x);
}

__global__ void __launch_bounds__(NT, 1)
vanilla_lstm_kernel(const float* __restrict__ obs,
                    const float* __restrict__ W_emb,  const float* __restrict__ b_emb,
                    const float* __restrict__ Wih_e,  const float* __restrict__ Whh_e,
                    const float* __restrict__ bih_e,  const float* __restrict__ bhh_e,
                    const float* __restrict__ Wih_d,  const float* __restrict__ Whh_d,
                    const float* __restrict__ bih_d,  const float* __restrict__ bhh_d,
                    const float* __restrict__ W_fc,   const float* __restrict__ b_fc,
                    float* __restrict__ out, int pred_len)
{
    extern __shared__ float sm[];
    float* sW    = sm + OFF_W;
    float* sBias = sm + OFF_BIAS;
    float* sWe   = sm + OFF_WE;
    float* sBe   = sm + OFF_BE;
    float* sWfc  = sm + OFF_WFC;
    float* sBfc  = sm + OFF_BFC;

    const int tid  = threadIdx.x;
    const int lane = tid & 31;
    const int w    = tid >> 5;
    const int b0   = blockIdx.x * MB;

    // per-warp strips: [64 k rows][8 cols]
    float4* xW4 = (float4*)(sm + OFF_X) + w * 128;   // 2 float4 per k row
    float4* hW4 = (float4*)(sm + OFF_H) + w * 128;
    float*  oW  = sm + OFF_OBS + w * 40 * CC;

    // ---- stage small params ----
    if (tid < 128) sWe[tid] = W_emb[(tid & 63) * 2 + (tid >> 6)];
    if (tid < 64)  sBe[tid] = b_emb[tid];
    if (tid < 128) sWfc[tid] = W_fc[tid];
    if (tid < 2)   sBfc[tid] = b_fc[tid];

    // obs: strip[w][r][c] with c = b & 7, w = b >> 3
    for (int i = tid; i < MB * 40; i += NT) {
        int b = i / 40, r = i % 40;
        sm[OFF_OBS + (b >> 3) * 40 * CC + r * CC + (b & 7)] =
            obs[(size_t)(b0 + b) * 40 + r];
    }

    // ---- weight staging, lane-swizzled ----
    auto stageW = [&](const float* Wih, const float* Whh,
                      const float* bih, const float* bhh) {
        for (int i = tid; i < GATES * 64; i += NT) {
            int row = i >> 6, k = i & 63;
            int g = row >> 6, rem = row & 63;
            int l = rem >> 1, d = rem & 1;
            int sz = (l >> 2) & 1;
            int phys = (2 * l + ((g >> 1) ^ sz)) * 4 + (g & 1) * 2 + d;
            sW[k * GATES + phys]        = Wih[i];
            sW[(64 + k) * GATES + phys] = Whh[i];
        }
        for (int row = tid; row < GATES; row += NT) {
            int g = row >> 6, rem = row & 63;
            sBias[(rem >> 1) * 8 + g * 2 + (rem & 1)] = bih[row] + bhh[row];
        }
    };
    stageW(Wih_e, Whh_e, bih_e, bhh_e);
    __syncthreads();

    // ---- per-lane hoisted constants ----
    const int swz = (lane >> 2) & 1;
    const char* wAx = (const char*)sW + (2 * lane + swz) * 16;       // g0,g1
    const char* wBx = (const char*)sW + (2 * lane + 1 - swz) * 16;   // g2,g3
    const char* wAh = wAx + 64 * 1024;
    const char* wBh = wBx + 64 * 1024;

    const int e0 = 2 * lane, e1 = 2 * lane + 1;
    float we00 = sWe[e0], we01 = sWe[64 + e0], be0 = sBe[e0];
    float we10 = sWe[e1], we11 = sWe[64 + e1], be1 = sBe[e1];
    float wfc00 = sWfc[e0], wfc01 = sWfc[e1];
    float wfc10 = sWfc[64 + e0], wfc11 = sWfc[64 + e1];
    float bfc0 = sBfc[0], bfc1 = sBfc[1];

    ULL biasv[4];
    #pragma unroll
    for (int g = 0; g < 4; g++)
        biasv[g] = *(const ULL*)(sBias + lane * 8 + g * 2);

    // embedded x for lane's 2 e-rows x 8 cols
    float4 xa0, xa1, xb0, xb1;
    auto embed_regs = [&](const float* p0, const float* p1) {
        float va[8], vb[8];
        #pragma unroll
        for (int j = 0; j < 8; j++) {
            va[j] = fmaxf(fmaf(p0[j], we00, fmaf(p1[j], we01, be0)), 0.f);
            vb[j] = fmaxf(fmaf(p0[j], we10, fmaf(p1[j], we11, be1)), 0.f);
        }
        xa0 = make_float4(va[0], va[1], va[2], va[3]);
        xa1 = make_float4(va[4], va[5], va[6], va[7]);
        xb0 = make_float4(vb[0], vb[1], vb[2], vb[3]);
        xb1 = make_float4(vb[4], vb[5], vb[6], vb[7]);
    };
    auto embed_obs = [&](int tt) {
        float p0[8], p1[8];
        *(float4*)(p0)     = *(const float4*)(oW + (2 * tt) * CC);
        *(float4*)(p0 + 4) = *(const float4*)(oW + (2 * tt) * CC + 4);
        *(float4*)(p1)     = *(const float4*)(oW + (2 * tt + 1) * CC);
        *(float4*)(p1 + 4) = *(const float4*)(oW + (2 * tt + 1) * CC + 4);
        embed_regs(p0, p1);
    };
    auto store_x = [&]() {
        xW4[2 * e0] = xa0; xW4[2 * e0 + 1] = xa1;
        xW4[2 * e1] = xb0; xW4[2 * e1 + 1] = xb1;
    };

    // GEMM over [k0,k1) for 8 cols
    auto gemm_part = [&](const float4* src, const char* wA, const char* wB,
                         ULL a[4][8], int k0, int k1) {
        #pragma unroll 4
        for (int k = k0; k < k1; k++) {
            float4 xlo = src[2 * k];
            float4 xhi = src[2 * k + 1];
            ULL xq[8];
            PACK_DUP(xq[0], __float_as_uint(xlo.x));
            PACK_DUP(xq[1], __float_as_uint(xlo.y));
            PACK_DUP(xq[2], __float_as_uint(xlo.z));
            PACK_DUP(xq[3], __float_as_uint(xlo.w));
            PACK_DUP(xq[4], __float_as_uint(xhi.x));
            PACK_DUP(xq[5], __float_as_uint(xhi.y));
            PACK_DUP(xq[6], __float_as_uint(xhi.z));
            PACK_DUP(xq[7], __float_as_uint(xhi.w));
            float4 w01 = *(const float4*)(wA + k * 1024);
            float4 w23 = *(const float4*)(wB + k * 1024);
            ULL wq0 = *(ULL*)&w01.x, wq1 = *(ULL*)&w01.z;
            ULL wq2 = *(ULL*)&w23.x, wq3 = *(ULL*)&w23.z;
            #pragma unroll
            for (int b = 0; b < 8; b++) {
                FMA_F32X2(a[0][b], wq0, xq[b], a[0][b]);
                FMA_F32X2(a[1][b], wq1, xq[b], a[1][b]);
                FMA_F32X2(a[2][b], wq2, xq[b], a[2][b]);
                FMA_F32X2(a[3][b], wq3, xq[b], a[3][b]);
            }
        }
    };

    float c[2][8], hv[2][8];
    #pragma unroll
    for (int d = 0; d < 2; d++)
        #pragma unroll
        for (int b = 0; b < 8; b++) c[d][b] = 0.0f;

    auto epi_col = [&](ULL a[4][8], int b) {
        unsigned i0, i1, f0, f1, g0, g1, o0, o1;
        UNPACK2(i0, i1, a[0][b]);
        UNPACK2(f0, f1, a[1][b]);
        UNPACK2(g0, g1, a[2][b]);
        UNPACK2(o0, o1, a[3][b]);
        {
            float ig = sigf(__uint_as_float(i0));
            float fg = sigf(__uint_as_float(f0));
            float gg = tanh_(__uint_as_float(g0));
            float og = sigf(__uint_as_float(o0));
            float cn = fmaf(fg, c[0][b], ig * gg);
            c[0][b] = cn;
            hv[0][b] = og * tanh_(cn);
        }
        {
            float ig = sigf(__uint_as_float(i1));
            float fg = sigf(__uint_as_float(f1));
            float gg = tanh_(__uint_as_float(g1));
            float og = sigf(__uint_as_float(o1));
            float cn = fmaf(fg, c[1][b], ig * gg);
            c[1][b] = cn;
            hv[1][b] = og * tanh_(cn);
        }
    };
    auto store_h = [&]() {
        hW4[2 * e0]     = make_float4(hv[0][0], hv[0][1], hv[0][2], hv[0][3]);
        hW4[2 * e0 + 1] = make_float4(hv[0][4], hv[0][5], hv[0][6], hv[0][7]);
        hW4[2 * e1]     = make_float4(hv[1][0], hv[1][1], hv[1][2], hv[1][3]);
        hW4[2 * e1 + 1] = make_float4(hv[1][4], hv[1][5], hv[1][6], hv[1][7]);
    };

    ULL acc1[4][8], acc2[4][8];

    // ---- prologue: acc1 = bias + Wih.x_0 (h_0 = 0 so no hGEMM) ----
    embed_obs(0);
    store_x();
    __syncwarp();
    #pragma unroll
    for (int g = 0; g < 4; g++)
        #pragma unroll
        for (int b = 0; b < 8; b++) acc1[g][b] = biasv[g];
    gemm_part(xW4, wAx, wBx, acc1, 0, 64);
    __syncwarp();
    embed_obs(1);
    store_x();                       // strip now holds x_1
    __syncwarp();

    // ================= encoder: t = 0..19 =================
    for (int t = 0; t < OBS_; t++) {
        if (t > 0) gemm_part(hW4, wAh, wBh, acc1, 0, 64);

        if (t < OBS_ - 1) {
            // interleave epilogue(t) with xGEMM(t+1): chunks let ptxas blend
            #pragma unroll
            for (int g = 0; g < 4; g++)
                #pragma unroll
                for (int b = 0; b < 8; b++) acc2[g][b] = biasv[g];
            epi_col(acc1, 0); epi_col(acc1, 1);
            gemm_part(xW4, wAx, wBx, acc2, 0, 16);
            epi_col(acc1, 2); epi_col(acc1, 3);
            gemm_part(xW4, wAx, wBx, acc2, 16, 32);
            epi_col(acc1, 4); epi_col(acc1, 5);
            gemm_part(xW4, wAx, wBx, acc2, 32, 48);
            epi_col(acc1, 6); epi_col(acc1, 7);
            gemm_part(xW4, wAx, wBx, acc2, 48, 64);
        } else {
            #pragma unroll
            for (int b = 0; b < 8; b++) epi_col(acc1, b);
        }

        __syncwarp();                 // all lanes done reading strips
        store_h();
        if (t + 2 < OBS_) {           // prepare x_{t+2}; t=18/19 keep x_19
            embed_obs(t + 2);
            store_x();
        }
        __syncwarp();

        if (t < OBS_ - 1) {
            #pragma unroll
            for (int g = 0; g < 4; g++)
                #pragma unroll
                for (int b = 0; b < 8; b++) acc1[g][b] = acc2[g][b];
        }
    }

    // ---- enc -> dec weight swap (the only block-wide syncs) ----
    __syncthreads();
    stageW(Wih_d, Whh_d, bih_d, bhh_d);
    __syncthreads();
    #pragma unroll
    for (int g = 0; g < 4; g++)
        biasv[g] = *(const ULL*)(sBias + lane * 8 + g * 2);

    // ================= decoder =================
    for (int td = 0; td < pred_len; td++) {
        #pragma unroll
        for (int g = 0; g < 4; g++)
            #pragma unroll
            for (int b = 0; b < 8; b++) acc1[g][b] = biasv[g];
        gemm_part(xW4, wAx, wBx, acc1, 0, 64);
        gemm_part(hW4, wAh, wBh, acc1, 0, 64);

        #pragma unroll
        for (int b = 0; b < 8; b++) epi_col(acc1, b);

        // FC: 16-value butterfly over 64 hidden (2 per lane)
        float r[16];
        #pragma unroll
        for (int b = 0; b < 8; b++) {
            r[b]     = fmaf(hv[0][b], wfc00, hv[1][b] * wfc01);
            r[8 + b] = fmaf(hv[0][b], wfc10, hv[1][b] * wfc11);
        }
        #pragma unroll
        for (int off = 16; off >= 1; off >>= 1)
            #pragma unroll
            for (int j = 0; j < 16; j++)
                r[j] += __shfl_xor_sync(0xffffffffu, r[j], off);
        float p0[8], p1[8];
        #pragma unroll
        for (int b = 0; b < 8; b++) { p0[b] = r[b] + bfc0; p1[b] = r[8 + b] + bfc1; }

        if (lane < 8) {
            float o0v = 0.f, o1v = 0.f;
            #pragma unroll
            for (int b = 0; b < 8; b++)
                if (lane == b) { o0v = p0[b]; o1v = p1[b]; }
            size_t o = ((size_t)(b0 + w * 8 + lane) * pred_len + td) * 2;
            *(float2*)(out + o) = make_float2(o0v, o1v);
        }

        if (td < pred_len - 1) {
            embed_regs(p0, p1);
            __syncwarp();
            store_h();
            store_x();
            __syncwarp();
        }
    }
}

extern "C" void kernel_launch(void* const* d_in, const int* in_sizes, int n_in,
                              void* d_out, int out_size)
{
    const float* obs   = (const float*)d_in[0];
    const float* W_emb = (const float*)d_in[1];
    const float* b_emb = (const float*)d_in[2];
    const float* Wih_e = (const float*)d_in[3];
    const float* Whh_e = (const float*)d_in[4];
    const float* bih_e = (const float*)d_in[5];
    const float* bhh_e = (const float*)d_in[6];
    const float* Wih_d = (const float*)d_in[7];
    const float* Whh_d = (const float*)d_in[8];
    const float* bih_d = (const float*)d_in[9];
    const float* bhh_d = (const float*)d_in[10];
    const float* W_fc  = (const float*)d_in[11];
    const float* b_fc  = (const float*)d_in[12];
    float* out = (float*)d_out;

    int B = in_sizes[0] / (OBS_ * 2);
    int pred_len = out_size / (B * 2);

    cudaFuncSetAttribute(vanilla_lstm_kernel,
                         cudaFuncAttributeMaxDynamicSharedMemorySize, SMEM_BYTES);

    int grid = B / MB;
    vanilla_lstm_kernel<<<grid, NT, SMEM_BYTES>>>(
        obs, W_emb, b_emb, Wih_e, Whh_e, bih_e, bhh_e,
        Wih_d, Whh_d, bih_d, bhh_d, W_fc, b_fc, out, pred_len);
}